// round 1
// baseline (speedup 1.0000x reference)
#include <cuda_runtime.h>
#include <math.h>

#define T_STEPS 128
#define BATCH   2048
#define FEAT    84
#define ENC_C   64
#define NH      2048            // h/c vector length = 128 ch * 16 spatial
#define KP      2176            // GEMM K: 2048 (h) + 64 (enc->i) + 64 (enc->f)

// ---------------- device scratch (static; no runtime allocation) ----------------
__device__ float g_enc[(long)BATCH * T_STEPS * ENC_C];   // 64 MB
__device__ float g_h[2][(long)BATCH * NH];               // 32 MB ping-pong
__device__ float g_c[(long)BATCH * NH];                  // 16 MB
__device__ float g_Wcat[(long)KP * NH];                  // 17.8 MB combined weight
__device__ float g_Weff[1024 * 64];                      // collapsed linear weight
__device__ float g_bias[4 * NH];                         // i,f,o,g biases

// ---------------- encoder: x[B*T,84] -> enc[B*T,64] (conv center tap + BN + relu)
__global__ void encoder_kernel(const float* __restrict__ x,
                               const float* __restrict__ w,   // [64,84,3]
                               const float* __restrict__ b,
                               const float* __restrict__ gamma,
                               const float* __restrict__ beta,
                               const float* __restrict__ mean,
                               const float* __restrict__ var) {
    __shared__ float xs[4][FEAT];
    __shared__ float ws[ENC_C][85];    // padded: 85 coprime w/ 32 banks
    int tid = threadIdx.x;             // 256
    int c = tid & 63, row = tid >> 6;
    long bt0 = (long)blockIdx.x * 4;

    for (int i = tid; i < ENC_C * FEAT; i += 256) {
        int cc = i / FEAT, f = i - cc * FEAT;
        ws[cc][f] = w[(cc * FEAT + f) * 3 + 1];   // center tap only
    }
    for (int i = tid; i < 4 * FEAT; i += 256) {
        int r = i / FEAT, f = i - r * FEAT;
        xs[r][f] = x[(bt0 + r) * FEAT + f];
    }
    __syncthreads();

    float acc = 0.f;
#pragma unroll 4
    for (int f = 0; f < FEAT; f++) acc += xs[row][f] * ws[c][f];
    float s = gamma[c] * rsqrtf(var[c] + 1e-5f);
    float v = (acc + b[c] - mean[c]) * s + beta[c];
    g_enc[(bt0 + row) * ENC_C + c] = fmaxf(v, 0.f);
}

// ---------------- W_eff[o][c] = sum_{j<16} lin_w[o][c*16+j]
__global__ void weff_kernel(const float* __restrict__ lin_w) {
    int idx = blockIdx.x * blockDim.x + threadIdx.x;
    if (idx >= 1024 * 64) return;
    int o = idx >> 6, c = idx & 63;
    float s = 0.f;
#pragma unroll
    for (int j = 0; j < 16; j++) s += lin_w[o * 1024 + c * 16 + j];
    g_Weff[o * 64 + c] = s;
}

// ---------------- Wcat rows 0..2047: dense conv weights, A[m][k] = h[m][k]
__global__ void wcat_conv_kernel(const float* __restrict__ cw) {
    int n = blockIdx.x * blockDim.x + threadIdx.x;   // 0..2047
    int k = blockIdx.y;                              // 0..2047
    int oc = n >> 4, p = n & 15;
    int base, il, q;
    if (k < 512)       { base = 128; il = 16 + (k >> 4); q = k & 15; }          // f: h ch 0..31
    else if (k < 1280) { int k2 = k - 512;  base = 256; il = k2 >> 4; q = k2 & 15; } // o: h 32..79
    else               { int k3 = k - 1280; base = 384; il = k3 >> 4; q = k3 & 15; } // g: h 80..127
    int dy = (q >> 2) - (p >> 2) + 1, dx = (q & 3) - (p & 3) + 1;
    float v = 0.f;
    if (dy >= 0 && dy < 3 && dx >= 0 && dx < 3)
        v = cw[((base + oc) * 48 + il) * 9 + dy * 3 + dx];
    g_Wcat[(long)k * NH + n] = v;
}

// ---------------- Wcat rows 2048..2175: enc->gate(i) and enc->gate(f) collapsed weights
__global__ void wcat_enc_kernel(const float* __restrict__ cw) {
    int n = blockIdx.x * blockDim.x + threadIdx.x;   // 0..2047
    int r = blockIdx.y;                              // 0..127
    int oc = n >> 4, p = n & 15;
    int py = p >> 2, px = p & 3;
    float acc = 0.f;
    if (r < 64) {                 // gate i: x channels 0..47, enc channel c=r
        int c = r;
        for (int ic = 0; ic < 48; ic++)
            for (int dy = 0; dy < 3; dy++) {
                int iy = py + dy - 1; if (iy < 0 || iy > 3) continue;
                for (int dx = 0; dx < 3; dx++) {
                    int ix = px + dx - 1; if (ix < 0 || ix > 3) continue;
                    acc += cw[(oc * 48 + ic) * 9 + dy * 3 + dx] *
                           g_Weff[(ic * 16 + iy * 4 + ix) * 64 + c];
                }
            }
    } else {                      // gate f x-part: x channels 48..63, enc channel c=r-64
        int c = r - 64;
        for (int il = 0; il < 16; il++)
            for (int dy = 0; dy < 3; dy++) {
                int iy = py + dy - 1; if (iy < 0 || iy > 3) continue;
                for (int dx = 0; dx < 3; dx++) {
                    int ix = px + dx - 1; if (ix < 0 || ix > 3) continue;
                    acc += cw[((128 + oc) * 48 + il) * 9 + dy * 3 + dx] *
                           g_Weff[((48 + il) * 16 + iy * 4 + ix) * 64 + c];
                }
            }
    }
    g_Wcat[(long)(2048 + r) * NH + n] = acc;
}

// ---------------- per-gate biases (lin_b flows through the conv for i and f)
__global__ void bias_kernel(const float* __restrict__ cw,
                            const float* __restrict__ cb,
                            const float* __restrict__ lb) {
    int n = blockIdx.x * blockDim.x + threadIdx.x;
    if (n >= NH) return;
    int oc = n >> 4, p = n & 15, py = p >> 2, px = p & 3;
    float bi = cb[oc], bf = cb[128 + oc];
    for (int dy = 0; dy < 3; dy++) {
        int iy = py + dy - 1; if (iy < 0 || iy > 3) continue;
        for (int dx = 0; dx < 3; dx++) {
            int ix = px + dx - 1; if (ix < 0 || ix > 3) continue;
            int q = iy * 4 + ix;
            for (int ic = 0; ic < 48; ic++)
                bi += cw[(oc * 48 + ic) * 9 + dy * 3 + dx] * lb[ic * 16 + q];
            for (int il = 0; il < 16; il++)
                bf += cw[((128 + oc) * 48 + il) * 9 + dy * 3 + dx] * lb[(48 + il) * 16 + q];
        }
    }
    g_bias[0 * NH + n] = bi;
    g_bias[1 * NH + n] = bf;
    g_bias[2 * NH + n] = cb[256 + oc];
    g_bias[3 * NH + n] = cb[384 + oc];
}

// ---------------- zero h0 and c0
__global__ void zero_kernel() {
    int idx = blockIdx.x * blockDim.x + threadIdx.x;
    int total = BATCH * NH;
    for (int i = idx; i < total; i += gridDim.x * blockDim.x) {
        g_h[0][i] = 0.f;
        g_c[i] = 0.f;
    }
}

// ---------------- fused recurrent step: block GEMM (4 gate segments) + LSTM update
__device__ __forceinline__ void mma16(float (&acc)[16],
                                      const float* __restrict__ As,
                                      const float* __restrict__ Bs,
                                      int ty, int tx) {
#pragma unroll
    for (int kk = 0; kk < 16; kk++) {
        float4 a4 = *(const float4*)(As + kk * 68 + ty * 4);
        float4 b4 = *(const float4*)(Bs + kk * 64 + tx * 4);
        acc[0]  += a4.x * b4.x; acc[1]  += a4.x * b4.y; acc[2]  += a4.x * b4.z; acc[3]  += a4.x * b4.w;
        acc[4]  += a4.y * b4.x; acc[5]  += a4.y * b4.y; acc[6]  += a4.y * b4.z; acc[7]  += a4.y * b4.w;
        acc[8]  += a4.z * b4.x; acc[9]  += a4.z * b4.y; acc[10] += a4.z * b4.z; acc[11] += a4.z * b4.w;
        acc[12] += a4.w * b4.x; acc[13] += a4.w * b4.y; acc[14] += a4.w * b4.z; acc[15] += a4.w * b4.w;
    }
}

__global__ __launch_bounds__(256, 2) void step_kernel(int t) {
    __shared__ float As[16 * 68];
    __shared__ float Bs[16 * 64];
    const float* __restrict__ h_in = g_h[t & 1];
    float* __restrict__ h_out = g_h[(t + 1) & 1];

    int tid = threadIdx.x;
    int tx = tid & 15, ty = tid >> 4;
    int m0 = blockIdx.y * 64, n0 = blockIdx.x * 64;
    int aml = tid >> 2, akl = (tid & 3) * 4;
    int bkr = tid >> 4, bnl = (tid & 15) * 4;

    float aI[16], aF[16], aO[16], aG[16];
#pragma unroll
    for (int i = 0; i < 16; i++) { aI[i] = 0.f; aF[i] = 0.f; aO[i] = 0.f; aG[i] = 0.f; }

    for (int k0 = 0; k0 < KP; k0 += 16) {
        float4 av;
        if (k0 < 2048) {
            av = *(const float4*)&h_in[(m0 + aml) * NH + k0 + akl];
        } else {
            int cb = (k0 < 2112) ? (k0 - 2048) : (k0 - 2112);
            av = *(const float4*)&g_enc[(long)(m0 + aml) * (T_STEPS * ENC_C) + t * ENC_C + cb + akl];
        }
        As[(akl + 0) * 68 + aml] = av.x;
        As[(akl + 1) * 68 + aml] = av.y;
        As[(akl + 2) * 68 + aml] = av.z;
        As[(akl + 3) * 68 + aml] = av.w;
        *(float4*)&Bs[bkr * 64 + bnl] = *(const float4*)&g_Wcat[(long)(k0 + bkr) * NH + n0 + bnl];
        __syncthreads();

        // segment -> gate (boundaries all multiples of 16)
        if (k0 < 512)        { mma16(aF, As, Bs, ty, tx); }
        else if (k0 < 1280)  { mma16(aO, As, Bs, ty, tx); }
        else if (k0 < 2048)  { mma16(aG, As, Bs, ty, tx); }
        else if (k0 < 2112)  { mma16(aI, As, Bs, ty, tx); }
        else                 { mma16(aF, As, Bs, ty, tx); }
        __syncthreads();
    }

#pragma unroll
    for (int i = 0; i < 4; i++) {
        int m = m0 + ty * 4 + i;
#pragma unroll
        for (int j = 0; j < 4; j++) {
            int n = n0 + tx * 4 + j;
            int id = i * 4 + j;
            float pi = aI[id] + g_bias[n];
            float pf = aF[id] + g_bias[NH + n];
            float po = aO[id] + g_bias[2 * NH + n];
            float pg = aG[id] + g_bias[3 * NH + n];
            float si = 1.f / (1.f + __expf(-pi));
            float sf = 1.f / (1.f + __expf(-pf));
            float so = 1.f / (1.f + __expf(-po));
            float tg = tanhf(pg);
            long  idx = (long)m * NH + n;
            float cn = sf * g_c[idx] + si * tg;
            g_c[idx] = cn;
            h_out[idx] = so * tanhf(cn);
        }
    }
}

// ---------------- classifier: h_last[2048,2048] -> relu FC 128 -> FC 2
__global__ void cls_kernel(const float* __restrict__ w1, const float* __restrict__ b1,
                           const float* __restrict__ w2, const float* __restrict__ b2,
                           float* __restrict__ out) {
    __shared__ float hs[4][NH];
    __shared__ float hid[4][128];
    int tid = threadIdx.x;   // 128
    int b0 = blockIdx.x * 4;
    const float* hlast = g_h[0];   // after 128 steps h lives in buffer 0

    for (int i = tid; i < 4 * NH; i += 128)
        hs[i >> 11][i & 2047] = hlast[(long)(b0 + (i >> 11)) * NH + (i & 2047)];
    __syncthreads();

    int wid = tid >> 5, lane = tid & 31;
    for (int jj = 0; jj < 32; jj++) {
        int j = wid * 32 + jj;
        float p0 = 0.f, p1 = 0.f, p2 = 0.f, p3 = 0.f;
        const float* wr = w1 + (long)j * NH;
        for (int k = lane; k < NH; k += 32) {
            float wv = wr[k];
            p0 += wv * hs[0][k]; p1 += wv * hs[1][k];
            p2 += wv * hs[2][k]; p3 += wv * hs[3][k];
        }
#pragma unroll
        for (int off = 16; off; off >>= 1) {
            p0 += __shfl_xor_sync(0xffffffffu, p0, off);
            p1 += __shfl_xor_sync(0xffffffffu, p1, off);
            p2 += __shfl_xor_sync(0xffffffffu, p2, off);
            p3 += __shfl_xor_sync(0xffffffffu, p3, off);
        }
        if (lane == 0) {
            float bb = b1[j];
            hid[0][j] = fmaxf(p0 + bb, 0.f);
            hid[1][j] = fmaxf(p1 + bb, 0.f);
            hid[2][j] = fmaxf(p2 + bb, 0.f);
            hid[3][j] = fmaxf(p3 + bb, 0.f);
        }
    }
    __syncthreads();
    if (tid < 8) {
        int r = tid >> 1, k2 = tid & 1;
        float s = b2[k2];
        for (int j = 0; j < 128; j++) s += hid[r][j] * w2[k2 * 128 + j];
        out[(b0 + r) * 2 + k2] = s;
    }
}

extern "C" void kernel_launch(void* const* d_in, const int* in_sizes, int n_in,
                              void* d_out, int out_size) {
    const float* x        = (const float*)d_in[0];
    const float* conv1d_w = (const float*)d_in[1];
    const float* conv1d_b = (const float*)d_in[2];
    const float* bn_gamma = (const float*)d_in[3];
    const float* bn_beta  = (const float*)d_in[4];
    const float* bn_mean  = (const float*)d_in[5];
    const float* bn_var   = (const float*)d_in[6];
    const float* lin_w    = (const float*)d_in[7];
    const float* lin_b    = (const float*)d_in[8];
    const float* cell_w   = (const float*)d_in[9];
    const float* cell_b   = (const float*)d_in[10];
    const float* cls1_w   = (const float*)d_in[11];
    const float* cls1_b   = (const float*)d_in[12];
    const float* cls2_w   = (const float*)d_in[13];
    const float* cls2_b   = (const float*)d_in[14];
    float* out = (float*)d_out;

    zero_kernel<<<4096, 256>>>();
    encoder_kernel<<<BATCH * T_STEPS / 4, 256>>>(x, conv1d_w, conv1d_b,
                                                 bn_gamma, bn_beta, bn_mean, bn_var);
    weff_kernel<<<256, 256>>>(lin_w);
    { dim3 g(8, 2048); wcat_conv_kernel<<<g, 256>>>(cell_w); }
    { dim3 g(8, 128);  wcat_enc_kernel<<<g, 256>>>(cell_w); }
    bias_kernel<<<8, 256>>>(cell_w, cell_b, lin_b);

    dim3 sg(32, 32);   // N tiles x M tiles
    for (int t = 0; t < T_STEPS; t++)
        step_kernel<<<sg, 256>>>(t);

    cls_kernel<<<512, 128>>>(cls1_w, cls1_b, cls2_w, cls2_b, out);
}

// round 3
// speedup vs baseline: 2.7476x; 2.7476x over previous
#include <cuda_runtime.h>
#include <cuda_bf16.h>
#include <cstdint>
#include <math.h>

#define T_STEPS 128
#define BATCH   2048
#define FEAT    84
#define ENC_C   64
#define NH      2048            // h/c vector length = 128 ch * 16 spatial
#define KP      2176            // Wb K rows: 2048 (h) + 64 (enc->i) + 64 (enc->f)
#define TE      (T_STEPS * 64)  // enc row stride (elements)

// SMEM: 2 buffers x 4 planes (Ah, Al, Bh, Bl), each plane 128 rows x 144B (64 bf16 + 16B pad)
#define PLANE_B   18432
#define BUF_B     73728
#define STEP_SMEM 147456

// ---------------- device scratch (static; no runtime allocation) ----------------
__device__ __nv_bfloat16 g_encH[(long)BATCH * T_STEPS * ENC_C];  // enc hi plane
__device__ __nv_bfloat16 g_encL[(long)BATCH * T_STEPS * ENC_C];  // enc lo plane
__device__ __nv_bfloat16 g_hH[2][(long)BATCH * NH];              // h hi, ping-pong
__device__ __nv_bfloat16 g_hL[2][(long)BATCH * NH];              // h lo
__device__ float g_c[(long)BATCH * NH];                          // cell state fp32
__device__ __nv_bfloat16 g_WbH[(long)NH * KP];                   // B[n][k] hi
__device__ __nv_bfloat16 g_WbL[(long)NH * KP];                   // B[n][k] lo
__device__ float g_pre[(long)4 * BATCH * NH];                    // gate preacts i,f,o,g
__device__ float g_Weff[1024 * 64];
__device__ float g_bias[4 * NH];

// ================= PTX helpers (baseline sm_103 — no tcgen05) =================
__device__ __forceinline__ uint32_t smem_to_u32(const void* p) {
    uint32_t a;
    asm("{ .reg .u64 t; cvta.to.shared.u64 t, %1; cvt.u32.u64 %0, t; }" : "=r"(a) : "l"(p));
    return a;
}
#define CP_ASYNC16(dst, src) \
    asm volatile("cp.async.cg.shared.global [%0], [%1], 16;" :: "r"(dst), "l"(src))
#define CP_COMMIT() asm volatile("cp.async.commit_group;" ::: "memory")
#define CP_WAIT(n)  asm volatile("cp.async.wait_group %0;" :: "n"(n) : "memory")
#define LDSM_X4(r0, r1, r2, r3, addr) \
    asm volatile("ldmatrix.sync.aligned.m8n8.x4.shared.b16 {%0,%1,%2,%3}, [%4];" \
        : "=r"(r0), "=r"(r1), "=r"(r2), "=r"(r3) : "r"(addr))
#define MMA16816(c0, c1, c2, c3, a0, a1, a2, a3, b0, b1) \
    asm volatile("mma.sync.aligned.m16n8k16.row.col.f32.bf16.bf16.f32 " \
        "{%0,%1,%2,%3}, {%4,%5,%6,%7}, {%8,%9}, {%0,%1,%2,%3};" \
        : "+f"(c0), "+f"(c1), "+f"(c2), "+f"(c3) \
        : "r"(a0), "r"(a1), "r"(a2), "r"(a3), "r"(b0), "r"(b1))

__device__ __forceinline__ uint32_t pack_bf2(__nv_bfloat16 a, __nv_bfloat16 b) {
    return (uint32_t)__bfloat16_as_ushort(a) | ((uint32_t)__bfloat16_as_ushort(b) << 16);
}

// ---------------- encoder: x[B*T,84] -> enc hi/lo planes
__global__ void encoder_kernel(const float* __restrict__ x,
                               const float* __restrict__ w,
                               const float* __restrict__ b,
                               const float* __restrict__ gamma,
                               const float* __restrict__ beta,
                               const float* __restrict__ mean,
                               const float* __restrict__ var) {
    __shared__ float xs[4][FEAT];
    __shared__ float ws[ENC_C][85];
    int tid = threadIdx.x;
    int c = tid & 63, row = tid >> 6;
    long bt0 = (long)blockIdx.x * 4;

    for (int i = tid; i < ENC_C * FEAT; i += 256) {
        int cc = i / FEAT, f = i - cc * FEAT;
        ws[cc][f] = w[(cc * FEAT + f) * 3 + 1];   // center tap only
    }
    for (int i = tid; i < 4 * FEAT; i += 256) {
        int r = i / FEAT, f = i - r * FEAT;
        xs[r][f] = x[(bt0 + r) * FEAT + f];
    }
    __syncthreads();

    float acc = 0.f;
#pragma unroll 4
    for (int f = 0; f < FEAT; f++) acc += xs[row][f] * ws[c][f];
    float s = gamma[c] * rsqrtf(var[c] + 1e-5f);
    float v = fmaxf((acc + b[c] - mean[c]) * s + beta[c], 0.f);
    __nv_bfloat16 hi = __float2bfloat16_rn(v);
    long idx = (bt0 + row) * ENC_C + c;
    g_encH[idx] = hi;
    g_encL[idx] = __float2bfloat16_rn(v - __bfloat162float(hi));
}

// ---------------- W_eff[o][c] = sum_{j<16} lin_w[o][c*16+j]
__global__ void weff_kernel(const float* __restrict__ lin_w) {
    int idx = blockIdx.x * blockDim.x + threadIdx.x;
    if (idx >= 1024 * 64) return;
    int o = idx >> 6, c = idx & 63;
    float s = 0.f;
#pragma unroll
    for (int j = 0; j < 16; j++) s += lin_w[o * 1024 + c * 16 + j];
    g_Weff[o * 64 + c] = s;
}

// ---------------- Wb rows 0..2047: dense conv weights -> bf16 hi/lo [n][k]
__global__ void wcat_conv_kernel(const float* __restrict__ cw) {
    int k = blockIdx.x * 256 + threadIdx.x;
    int n = blockIdx.y;
    int oc = n >> 4, p = n & 15;
    int base, il, q;
    if (k < 512)       { base = 128; il = 16 + (k >> 4); q = k & 15; }
    else if (k < 1280) { int k2 = k - 512;  base = 256; il = k2 >> 4; q = k2 & 15; }
    else               { int k3 = k - 1280; base = 384; il = k3 >> 4; q = k3 & 15; }
    int dy = (q >> 2) - (p >> 2) + 1, dx = (q & 3) - (p & 3) + 1;
    float v = 0.f;
    if (dy >= 0 && dy < 3 && dx >= 0 && dx < 3)
        v = cw[((base + oc) * 48 + il) * 9 + dy * 3 + dx];
    __nv_bfloat16 hi = __float2bfloat16_rn(v);
    long idx = (long)n * KP + k;
    g_WbH[idx] = hi;
    g_WbL[idx] = __float2bfloat16_rn(v - __bfloat162float(hi));
}

// ---------------- Wb rows 2048..2175: enc->i and enc->f collapsed weights
__global__ void wcat_enc_kernel(const float* __restrict__ cw) {
    int r = threadIdx.x;          // 0..127
    int n = blockIdx.x;           // 0..2047
    int oc = n >> 4, p = n & 15;
    int py = p >> 2, px = p & 3;
    float acc = 0.f;
    if (r < 64) {
        int c = r;
        for (int ic = 0; ic < 48; ic++)
            for (int dy = 0; dy < 3; dy++) {
                int iy = py + dy - 1; if (iy < 0 || iy > 3) continue;
                for (int dx = 0; dx < 3; dx++) {
                    int ix = px + dx - 1; if (ix < 0 || ix > 3) continue;
                    acc += cw[(oc * 48 + ic) * 9 + dy * 3 + dx] *
                           g_Weff[(ic * 16 + iy * 4 + ix) * 64 + c];
                }
            }
    } else {
        int c = r - 64;
        for (int il = 0; il < 16; il++)
            for (int dy = 0; dy < 3; dy++) {
                int iy = py + dy - 1; if (iy < 0 || iy > 3) continue;
                for (int dx = 0; dx < 3; dx++) {
                    int ix = px + dx - 1; if (ix < 0 || ix > 3) continue;
                    acc += cw[((128 + oc) * 48 + il) * 9 + dy * 3 + dx] *
                           g_Weff[((48 + il) * 16 + iy * 4 + ix) * 64 + c];
                }
            }
    }
    __nv_bfloat16 hi = __float2bfloat16_rn(acc);
    long idx = (long)n * KP + 2048 + r;
    g_WbH[idx] = hi;
    g_WbL[idx] = __float2bfloat16_rn(acc - __bfloat162float(hi));
}

// ---------------- per-gate biases
__global__ void bias_kernel(const float* __restrict__ cw,
                            const float* __restrict__ cb,
                            const float* __restrict__ lb) {
    int n = blockIdx.x * blockDim.x + threadIdx.x;
    if (n >= NH) return;
    int oc = n >> 4, p = n & 15, py = p >> 2, px = p & 3;
    float bi = cb[oc], bf = cb[128 + oc];
    for (int dy = 0; dy < 3; dy++) {
        int iy = py + dy - 1; if (iy < 0 || iy > 3) continue;
        for (int dx = 0; dx < 3; dx++) {
            int ix = px + dx - 1; if (ix < 0 || ix > 3) continue;
            int q = iy * 4 + ix;
            for (int ic = 0; ic < 48; ic++)
                bi += cw[(oc * 48 + ic) * 9 + dy * 3 + dx] * lb[ic * 16 + q];
            for (int il = 0; il < 16; il++)
                bf += cw[((128 + oc) * 48 + il) * 9 + dy * 3 + dx] * lb[(48 + il) * 16 + q];
        }
    }
    g_bias[0 * NH + n] = bi;
    g_bias[1 * NH + n] = bf;
    g_bias[2 * NH + n] = cb[256 + oc];
    g_bias[3 * NH + n] = cb[384 + oc];
}

// ---------------- zero h0 (both planes) and c0
__global__ void zero_kernel() {
    int idx = blockIdx.x * blockDim.x + threadIdx.x;
    int total = BATCH * NH;
    for (int i = idx; i < total; i += gridDim.x * blockDim.x) {
        g_hH[0][i] = __float2bfloat16_rn(0.f);
        g_hL[0][i] = __float2bfloat16_rn(0.f);
        g_c[i] = 0.f;
    }
}

// ================= Phase A: per-gate GEMM (mma.sync bf16, bf16x3 split) =================
// gate 0=i (K=64 enc), 1=f (K=512 h + 64 enc), 2=o (K=768), 3=g (K=768)
// CTA tile 128m x 128n, 8 warps (2m x 4n) of 64x32. Writes fp32 preacts.

__device__ __forceinline__ void stage_chunk(uint32_t sb, int buf, int tid,
        const __nv_bfloat16* __restrict__ aH, const __nv_bfloat16* __restrict__ aL,
        long astride,
        const __nv_bfloat16* __restrict__ bHp, const __nv_bfloat16* __restrict__ bLp) {
    uint32_t dbase = sb + buf * BUF_B;
#pragma unroll
    for (int i = 0; i < 16; i++) {
        int u = i * 256 + tid;
        int pl = u >> 10, r = (u >> 3) & 127, c = u & 7;
        uint32_t dst = dbase + pl * PLANE_B + r * 144 + c * 16;
        const __nv_bfloat16* src;
        if (pl == 0)      src = aH + (long)r * astride + c * 8;
        else if (pl == 1) src = aL + (long)r * astride + c * 8;
        else if (pl == 2) src = bHp + (long)r * KP + c * 8;
        else              src = bLp + (long)r * KP + c * 8;
        CP_ASYNC16(dst, src);
    }
}

__device__ __forceinline__ void compute_chunk(uint32_t sb, int buf, int lane,
                                              int wm, int wn, float acc[4][4][4]) {
    uint32_t Ab = sb + buf * BUF_B;
    uint32_t Bb = Ab + 2 * PLANE_B;
    uint32_t lrow = lane & 15, lcol = (lane >> 4) << 4;
#pragma unroll
    for (int kk = 0; kk < 4; kk++) {
        uint32_t aHf[4][4], aLf[4][4], bHf[4][2], bLf[4][2];
#pragma unroll
        for (int i = 0; i < 4; i++) {
            uint32_t ad = Ab + (wm + i * 16 + lrow) * 144 + kk * 32 + lcol;
            LDSM_X4(aHf[i][0], aHf[i][1], aHf[i][2], aHf[i][3], ad);
            LDSM_X4(aLf[i][0], aLf[i][1], aLf[i][2], aLf[i][3], ad + PLANE_B);
        }
#pragma unroll
        for (int jp = 0; jp < 2; jp++) {
            uint32_t bd = Bb + (wn + jp * 16 + lrow) * 144 + kk * 32 + lcol;
            uint32_t r0, r1, r2, r3;
            LDSM_X4(r0, r1, r2, r3, bd);
            bHf[2 * jp][0] = r0; bHf[2 * jp][1] = r2;
            bHf[2 * jp + 1][0] = r1; bHf[2 * jp + 1][1] = r3;
            LDSM_X4(r0, r1, r2, r3, bd + PLANE_B);
            bLf[2 * jp][0] = r0; bLf[2 * jp][1] = r2;
            bLf[2 * jp + 1][0] = r1; bLf[2 * jp + 1][1] = r3;
        }
#pragma unroll
        for (int i = 0; i < 4; i++)
#pragma unroll
            for (int j = 0; j < 4; j++) {
                MMA16816(acc[i][j][0], acc[i][j][1], acc[i][j][2], acc[i][j][3],
                         aHf[i][0], aHf[i][1], aHf[i][2], aHf[i][3], bHf[j][0], bHf[j][1]);
                MMA16816(acc[i][j][0], acc[i][j][1], acc[i][j][2], acc[i][j][3],
                         aHf[i][0], aHf[i][1], aHf[i][2], aHf[i][3], bLf[j][0], bLf[j][1]);
                MMA16816(acc[i][j][0], acc[i][j][1], acc[i][j][2], acc[i][j][3],
                         aLf[i][0], aLf[i][1], aLf[i][2], aLf[i][3], bHf[j][0], bHf[j][1]);
            }
    }
}

__global__ __launch_bounds__(256) void gate_gemm_kernel(int t) {
    extern __shared__ char smem[];
    uint32_t sb = smem_to_u32(smem);
    int tid = threadIdx.x, lane = tid & 31, wid = tid >> 5;
    int gate = blockIdx.z;
    int m0 = blockIdx.y << 7, n0 = blockIdx.x << 7;
    int nch = (gate == 0) ? 1 : (gate == 1) ? 9 : 12;
    int wm = (wid & 1) << 6, wn = (wid >> 1) << 5;

    const __nv_bfloat16* hHp = g_hH[t & 1];
    const __nv_bfloat16* hLp = g_hL[t & 1];

    float acc[4][4][4];
#pragma unroll
    for (int i = 0; i < 4; i++)
#pragma unroll
        for (int j = 0; j < 4; j++)
#pragma unroll
            for (int k = 0; k < 4; k++) acc[i][j][k] = 0.f;

    // k0 for chunk index
    auto k0_of = [&](int ch) -> int {
        if (gate == 0) return 2048;
        if (gate == 1) return (ch < 8) ? (ch << 6) : 2112;
        if (gate == 2) return 512 + (ch << 6);
        return 1280 + (ch << 6);
    };
    auto stage = [&](int buf, int k0) {
        const __nv_bfloat16 *aH, *aL;
        long astr;
        if (k0 < 2048) {
            aH = hHp + (long)m0 * NH + k0;
            aL = hLp + (long)m0 * NH + k0;
            astr = NH;
        } else {
            aH = g_encH + (long)m0 * TE + (long)t * 64;
            aL = g_encL + (long)m0 * TE + (long)t * 64;
            astr = TE;
        }
        stage_chunk(sb, buf, tid, aH, aL, astr,
                    g_WbH + (long)n0 * KP + k0, g_WbL + (long)n0 * KP + k0);
    };

    stage(0, k0_of(0));
    CP_COMMIT();
    for (int ch = 0; ch < nch; ch++) {
        if (ch + 1 < nch) {
            stage((ch + 1) & 1, k0_of(ch + 1));
            CP_COMMIT();
            CP_WAIT(1);
        } else {
            CP_WAIT(0);
        }
        __syncthreads();
        compute_chunk(sb, ch & 1, lane, wm, wn, acc);
        __syncthreads();
    }

    // write fp32 preacts
    float* prep = g_pre + (long)gate * BATCH * NH;
    int g = lane >> 2, tk = lane & 3;
#pragma unroll
    for (int i = 0; i < 4; i++) {
        int m = m0 + wm + i * 16 + g;
#pragma unroll
        for (int j = 0; j < 4; j++) {
            int n = n0 + wn + j * 8 + tk * 2;
            *(float2*)&prep[(long)m * NH + n]       = make_float2(acc[i][j][0], acc[i][j][1]);
            *(float2*)&prep[(long)(m + 8) * NH + n] = make_float2(acc[i][j][2], acc[i][j][3]);
        }
    }
}

// ================= Phase B: elementwise LSTM update =================
__global__ __launch_bounds__(256) void lstm_update_kernel(int t) {
    const long SZ = (long)BATCH * NH;
    long i4 = ((long)blockIdx.x * 256 + threadIdx.x) * 4;
    int n = (int)(i4 & (NH - 1));
    float4 vi = *(const float4*)&g_pre[i4];
    float4 vf = *(const float4*)&g_pre[SZ + i4];
    float4 vo = *(const float4*)&g_pre[2 * SZ + i4];
    float4 vg = *(const float4*)&g_pre[3 * SZ + i4];
    float4 bi = *(const float4*)&g_bias[n];
    float4 bf = *(const float4*)&g_bias[NH + n];
    float4 bo = *(const float4*)&g_bias[2 * NH + n];
    float4 bg = *(const float4*)&g_bias[3 * NH + n];
    float4 cc = *(const float4*)&g_c[i4];

    float pi[4] = {vi.x + bi.x, vi.y + bi.y, vi.z + bi.z, vi.w + bi.w};
    float pf[4] = {vf.x + bf.x, vf.y + bf.y, vf.z + bf.z, vf.w + bf.w};
    float po[4] = {vo.x + bo.x, vo.y + bo.y, vo.z + bo.z, vo.w + bo.w};
    float pg[4] = {vg.x + bg.x, vg.y + bg.y, vg.z + bg.z, vg.w + bg.w};
    float cv[4] = {cc.x, cc.y, cc.z, cc.w};
    float hn[4], cn[4];
#pragma unroll
    for (int j = 0; j < 4; j++) {
        float si = 1.f / (1.f + __expf(-pi[j]));
        float sf = 1.f / (1.f + __expf(-pf[j]));
        float so = 1.f / (1.f + __expf(-po[j]));
        float tg = tanhf(pg[j]);
        cn[j] = sf * cv[j] + si * tg;
        hn[j] = so * tanhf(cn[j]);
    }
    *(float4*)&g_c[i4] = make_float4(cn[0], cn[1], cn[2], cn[3]);

    __nv_bfloat16 hh[4], hl[4];
#pragma unroll
    for (int j = 0; j < 4; j++) {
        hh[j] = __float2bfloat16_rn(hn[j]);
        hl[j] = __float2bfloat16_rn(hn[j] - __bfloat162float(hh[j]));
    }
    int ob = (t + 1) & 1;
    *(uint2*)&g_hH[ob][i4] = make_uint2(pack_bf2(hh[0], hh[1]), pack_bf2(hh[2], hh[3]));
    *(uint2*)&g_hL[ob][i4] = make_uint2(pack_bf2(hl[0], hl[1]), pack_bf2(hl[2], hl[3]));
}

// ---------------- classifier: h_last[2048,2048] -> relu FC 128 -> FC 2
__global__ void cls_kernel(const float* __restrict__ w1, const float* __restrict__ b1,
                           const float* __restrict__ w2, const float* __restrict__ b2,
                           float* __restrict__ out) {
    __shared__ float hs[4][NH];
    __shared__ float hid[4][128];
    int tid = threadIdx.x;
    int b0 = blockIdx.x * 4;
    const __nv_bfloat16* hH = g_hH[0];   // after 128 steps (t=127 writes buf 0)
    const __nv_bfloat16* hL = g_hL[0];

    for (int i = tid; i < 4 * NH; i += 128) {
        long idx = (long)(b0 + (i >> 11)) * NH + (i & 2047);
        hs[i >> 11][i & 2047] = __bfloat162float(hH[idx]) + __bfloat162float(hL[idx]);
    }
    __syncthreads();

    int wid = tid >> 5, lane = tid & 31;
    for (int jj = 0; jj < 32; jj++) {
        int j = wid * 32 + jj;
        float p0 = 0.f, p1 = 0.f, p2 = 0.f, p3 = 0.f;
        const float* wr = w1 + (long)j * NH;
        for (int k = lane; k < NH; k += 32) {
            float wv = wr[k];
            p0 += wv * hs[0][k]; p1 += wv * hs[1][k];
            p2 += wv * hs[2][k]; p3 += wv * hs[3][k];
        }
#pragma unroll
        for (int off = 16; off; off >>= 1) {
            p0 += __shfl_xor_sync(0xffffffffu, p0, off);
            p1 += __shfl_xor_sync(0xffffffffu, p1, off);
            p2 += __shfl_xor_sync(0xffffffffu, p2, off);
            p3 += __shfl_xor_sync(0xffffffffu, p3, off);
        }
        if (lane == 0) {
            float bb = b1[j];
            hid[0][j] = fmaxf(p0 + bb, 0.f);
            hid[1][j] = fmaxf(p1 + bb, 0.f);
            hid[2][j] = fmaxf(p2 + bb, 0.f);
            hid[3][j] = fmaxf(p3 + bb, 0.f);
        }
    }
    __syncthreads();
    if (tid < 8) {
        int r = tid >> 1, k2 = tid & 1;
        float s = b2[k2];
        for (int j = 0; j < 128; j++) s += hid[r][j] * w2[k2 * 128 + j];
        out[(b0 + r) * 2 + k2] = s;
    }
}

extern "C" void kernel_launch(void* const* d_in, const int* in_sizes, int n_in,
                              void* d_out, int out_size) {
    const float* x        = (const float*)d_in[0];
    const float* conv1d_w = (const float*)d_in[1];
    const float* conv1d_b = (const float*)d_in[2];
    const float* bn_gamma = (const float*)d_in[3];
    const float* bn_beta  = (const float*)d_in[4];
    const float* bn_mean  = (const float*)d_in[5];
    const float* bn_var   = (const float*)d_in[6];
    const float* lin_w    = (const float*)d_in[7];
    const float* lin_b    = (const float*)d_in[8];
    const float* cell_w   = (const float*)d_in[9];
    const float* cell_b   = (const float*)d_in[10];
    const float* cls1_w   = (const float*)d_in[11];
    const float* cls1_b   = (const float*)d_in[12];
    const float* cls2_w   = (const float*)d_in[13];
    const float* cls2_b   = (const float*)d_in[14];
    float* out = (float*)d_out;

    static bool attr_set = false;
    if (!attr_set) {
        cudaFuncSetAttribute(gate_gemm_kernel,
                             cudaFuncAttributeMaxDynamicSharedMemorySize, STEP_SMEM);
        attr_set = true;
    }

    zero_kernel<<<4096, 256>>>();
    encoder_kernel<<<BATCH * T_STEPS / 4, 256>>>(x, conv1d_w, conv1d_b,
                                                 bn_gamma, bn_beta, bn_mean, bn_var);
    weff_kernel<<<256, 256>>>(lin_w);
    { dim3 g(8, 2048); wcat_conv_kernel<<<g, 256>>>(cell_w); }
    wcat_enc_kernel<<<2048, 128>>>(cell_w);
    bias_kernel<<<8, 256>>>(cell_w, cell_b, lin_b);

    dim3 gg(16, 16, 4);   // n-tiles, m-tiles, gates
    for (int t = 0; t < T_STEPS; t++) {
        gate_gemm_kernel<<<gg, 256, STEP_SMEM>>>(t);
        lstm_update_kernel<<<BATCH * NH / 4 / 256, 256>>>(t);
    }

    cls_kernel<<<512, 128>>>(cls1_w, cls1_b, cls2_w, cls2_b, out);
}

// round 7
// speedup vs baseline: 3.1023x; 1.1291x over previous
#include <cuda_runtime.h>
#include <cuda_bf16.h>
#include <cstdint>
#include <math.h>

#define T_STEPS 128
#define BATCH   2048
#define FEAT    84
#define ENC_C   64
#define NH      2048            // h/c vector length = 128 ch * 16 spatial
#define KP      2176            // Wb K rows: 2048 (h) + 64 (enc->i) + 64 (enc->f)
#define TE      (T_STEPS * 64)  // enc row stride (elements)

// SMEM: 2 buffers x 4 planes (Ah, Al, Bh, Bl); plane = 128 rows x 80B (32 bf16 + 16B pad)
#define PLANE_B   10240
#define BUF_B     40960
#define STEP_SMEM 81920

// ---------------- device scratch (static; no runtime allocation) ----------------
__device__ __nv_bfloat16 g_encH[(long)BATCH * T_STEPS * ENC_C];  // enc hi plane
__device__ __nv_bfloat16 g_encL[(long)BATCH * T_STEPS * ENC_C];  // enc lo plane
__device__ __nv_bfloat16 g_hH[2][(long)BATCH * NH];              // h hi, ping-pong
__device__ __nv_bfloat16 g_hL[2][(long)BATCH * NH];              // h lo
__device__ float g_c[(long)BATCH * NH];                          // cell state fp32
__device__ __nv_bfloat16 g_WbH[(long)NH * KP];                   // B[n][k] hi
__device__ __nv_bfloat16 g_WbL[(long)NH * KP];                   // B[n][k] lo
__device__ float g_pre[(long)4 * BATCH * NH];                    // gate preacts i,f,o,g
__device__ float g_Weff[1024 * 64];
__device__ float g_bias[4 * NH];

// ================= PTX helpers (baseline sm_103 — no tcgen05) =================
__device__ __forceinline__ uint32_t smem_to_u32(const void* p) {
    uint32_t a;
    asm("{ .reg .u64 t; cvta.to.shared.u64 t, %1; cvt.u32.u64 %0, t; }" : "=r"(a) : "l"(p));
    return a;
}
#define CP_ASYNC16(dst, src) \
    asm volatile("cp.async.cg.shared.global [%0], [%1], 16;" :: "r"(dst), "l"(src))
#define CP_COMMIT() asm volatile("cp.async.commit_group;" ::: "memory")
#define CP_WAIT(n)  asm volatile("cp.async.wait_group %0;" :: "n"(n) : "memory")
#define LDSM_X4(r0, r1, r2, r3, addr) \
    asm volatile("ldmatrix.sync.aligned.m8n8.x4.shared.b16 {%0,%1,%2,%3}, [%4];" \
        : "=r"(r0), "=r"(r1), "=r"(r2), "=r"(r3) : "r"(addr))
#define MMA16816(c0, c1, c2, c3, a0, a1, a2, a3, b0, b1) \
    asm volatile("mma.sync.aligned.m16n8k16.row.col.f32.bf16.bf16.f32 " \
        "{%0,%1,%2,%3}, {%4,%5,%6,%7}, {%8,%9}, {%0,%1,%2,%3};" \
        : "+f"(c0), "+f"(c1), "+f"(c2), "+f"(c3) \
        : "r"(a0), "r"(a1), "r"(a2), "r"(a3), "r"(b0), "r"(b1))

__device__ __forceinline__ uint32_t pack_bf2(__nv_bfloat16 a, __nv_bfloat16 b) {
    return (uint32_t)__bfloat16_as_ushort(a) | ((uint32_t)__bfloat16_as_ushort(b) << 16);
}

// ---------------- encoder: x[B*T,84] -> enc hi/lo planes
__global__ void encoder_kernel(const float* __restrict__ x,
                               const float* __restrict__ w,
                               const float* __restrict__ b,
                               const float* __restrict__ gamma,
                               const float* __restrict__ beta,
                               const float* __restrict__ mean,
                               const float* __restrict__ var) {
    __shared__ float xs[4][FEAT];
    __shared__ float ws[ENC_C][85];
    int tid = threadIdx.x;
    int c = tid & 63, row = tid >> 6;
    long bt0 = (long)blockIdx.x * 4;

    for (int i = tid; i < ENC_C * FEAT; i += 256) {
        int cc = i / FEAT, f = i - cc * FEAT;
        ws[cc][f] = w[(cc * FEAT + f) * 3 + 1];   // center tap only
    }
    for (int i = tid; i < 4 * FEAT; i += 256) {
        int r = i / FEAT, f = i - r * FEAT;
        xs[r][f] = x[(bt0 + r) * FEAT + f];
    }
    __syncthreads();

    float acc = 0.f;
#pragma unroll 4
    for (int f = 0; f < FEAT; f++) acc += xs[row][f] * ws[c][f];
    float s = gamma[c] * rsqrtf(var[c] + 1e-5f);
    float v = fmaxf((acc + b[c] - mean[c]) * s + beta[c], 0.f);
    __nv_bfloat16 hi = __float2bfloat16_rn(v);
    long idx = (bt0 + row) * ENC_C + c;
    g_encH[idx] = hi;
    g_encL[idx] = __float2bfloat16_rn(v - __bfloat162float(hi));
}

// ---------------- W_eff[o][c] = sum_{j<16} lin_w[o][c*16+j]
__global__ void weff_kernel(const float* __restrict__ lin_w) {
    int idx = blockIdx.x * blockDim.x + threadIdx.x;
    if (idx >= 1024 * 64) return;
    int o = idx >> 6, c = idx & 63;
    float s = 0.f;
#pragma unroll
    for (int j = 0; j < 16; j++) s += lin_w[o * 1024 + c * 16 + j];
    g_Weff[o * 64 + c] = s;
}

// ---------------- Wb rows 0..2047: dense conv weights -> bf16 hi/lo [n][k]
__global__ void wcat_conv_kernel(const float* __restrict__ cw) {
    int k = blockIdx.x * 256 + threadIdx.x;
    int n = blockIdx.y;
    int oc = n >> 4, p = n & 15;
    int base, il, q;
    if (k < 512)       { base = 128; il = 16 + (k >> 4); q = k & 15; }
    else if (k < 1280) { int k2 = k - 512;  base = 256; il = k2 >> 4; q = k2 & 15; }
    else               { int k3 = k - 1280; base = 384; il = k3 >> 4; q = k3 & 15; }
    int dy = (q >> 2) - (p >> 2) + 1, dx = (q & 3) - (p & 3) + 1;
    float v = 0.f;
    if (dy >= 0 && dy < 3 && dx >= 0 && dx < 3)
        v = cw[((base + oc) * 48 + il) * 9 + dy * 3 + dx];
    __nv_bfloat16 hi = __float2bfloat16_rn(v);
    long idx = (long)n * KP + k;
    g_WbH[idx] = hi;
    g_WbL[idx] = __float2bfloat16_rn(v - __bfloat162float(hi));
}

// ---------------- Wb rows 2048..2175: enc->i and enc->f collapsed weights
__global__ void wcat_enc_kernel(const float* __restrict__ cw) {
    int r = threadIdx.x;          // 0..127
    int n = blockIdx.x;           // 0..2047
    int oc = n >> 4, p = n & 15;
    int py = p >> 2, px = p & 3;
    float acc = 0.f;
    if (r < 64) {
        int c = r;
        for (int ic = 0; ic < 48; ic++)
            for (int dy = 0; dy < 3; dy++) {
                int iy = py + dy - 1; if (iy < 0 || iy > 3) continue;
                for (int dx = 0; dx < 3; dx++) {
                    int ix = px + dx - 1; if (ix < 0 || ix > 3) continue;
                    acc += cw[(oc * 48 + ic) * 9 + dy * 3 + dx] *
                           g_Weff[(ic * 16 + iy * 4 + ix) * 64 + c];
                }
            }
    } else {
        int c = r - 64;
        for (int il = 0; il < 16; il++)
            for (int dy = 0; dy < 3; dy++) {
                int iy = py + dy - 1; if (iy < 0 || iy > 3) continue;
                for (int dx = 0; dx < 3; dx++) {
                    int ix = px + dx - 1; if (ix < 0 || ix > 3) continue;
                    acc += cw[((128 + oc) * 48 + il) * 9 + dy * 3 + dx] *
                           g_Weff[((48 + il) * 16 + iy * 4 + ix) * 64 + c];
                }
            }
    }
    __nv_bfloat16 hi = __float2bfloat16_rn(acc);
    long idx = (long)n * KP + 2048 + r;
    g_WbH[idx] = hi;
    g_WbL[idx] = __float2bfloat16_rn(acc - __bfloat162float(hi));
}

// ---------------- per-gate biases
__global__ void bias_kernel(const float* __restrict__ cw,
                            const float* __restrict__ cb,
                            const float* __restrict__ lb) {
    int n = blockIdx.x * blockDim.x + threadIdx.x;
    if (n >= NH) return;
    int oc = n >> 4, p = n & 15, py = p >> 2, px = p & 3;
    float bi = cb[oc], bf = cb[128 + oc];
    for (int dy = 0; dy < 3; dy++) {
        int iy = py + dy - 1; if (iy < 0 || iy > 3) continue;
        for (int dx = 0; dx < 3; dx++) {
            int ix = px + dx - 1; if (ix < 0 || ix > 3) continue;
            int q = iy * 4 + ix;
            for (int ic = 0; ic < 48; ic++)
                bi += cw[(oc * 48 + ic) * 9 + dy * 3 + dx] * lb[ic * 16 + q];
            for (int il = 0; il < 16; il++)
                bf += cw[((128 + oc) * 48 + il) * 9 + dy * 3 + dx] * lb[(48 + il) * 16 + q];
        }
    }
    g_bias[0 * NH + n] = bi;
    g_bias[1 * NH + n] = bf;
    g_bias[2 * NH + n] = cb[256 + oc];
    g_bias[3 * NH + n] = cb[384 + oc];
}

// ---------------- zero h0 (both planes) and c0
__global__ void zero_kernel() {
    int idx = blockIdx.x * blockDim.x + threadIdx.x;
    int total = BATCH * NH;
    for (int i = idx; i < total; i += gridDim.x * blockDim.x) {
        g_hH[0][i] = __float2bfloat16_rn(0.f);
        g_hL[0][i] = __float2bfloat16_rn(0.f);
        g_c[i] = 0.f;
    }
}

// ================= Phase A: per-gate GEMM (mma.sync bf16, bf16x3 split) =================
// K-chunks of 32. gate 0=i (2 ch), 1=f (16 h + 2 enc), 2=o (24), 3=g (24).
// CTA tile 128m x 128n, 8 warps (2m x 4n) of 64x32, 2 CTAs/SM.

__device__ __forceinline__ void stage_chunk(uint32_t sb, int buf, int tid,
        const __nv_bfloat16* __restrict__ aH, const __nv_bfloat16* __restrict__ aL,
        long astride,
        const __nv_bfloat16* __restrict__ bHp, const __nv_bfloat16* __restrict__ bLp) {
    uint32_t dbase = sb + buf * BUF_B;
#pragma unroll
    for (int i = 0; i < 8; i++) {
        int u = i * 256 + tid;
        int pl = u >> 9, r = (u >> 2) & 127, c = u & 3;
        uint32_t dst = dbase + pl * PLANE_B + r * 80 + c * 16;
        const __nv_bfloat16* src;
        if (pl == 0)      src = aH + (long)r * astride + c * 8;
        else if (pl == 1) src = aL + (long)r * astride + c * 8;
        else if (pl == 2) src = bHp + (long)r * KP + c * 8;
        else              src = bLp + (long)r * KP + c * 8;
        CP_ASYNC16(dst, src);
    }
}

__device__ __forceinline__ void compute_chunk(uint32_t sb, int buf, int lane,
                                              int wm, int wn, float acc[4][4][4]) {
    uint32_t Ab = sb + buf * BUF_B;
    uint32_t Bb = Ab + 2 * PLANE_B;
    uint32_t lrow = lane & 15, lcol = (lane >> 4) << 4;
#pragma unroll
    for (int kk = 0; kk < 2; kk++) {
        uint32_t af[4][4], bHf[4][2], bLf[4][2];
        // B fragments first (both planes)
#pragma unroll
        for (int jp = 0; jp < 2; jp++) {
            uint32_t bd = Bb + (wn + jp * 16 + lrow) * 80 + kk * 32 + lcol;
            uint32_t r0, r1, r2, r3;
            LDSM_X4(r0, r1, r2, r3, bd);
            bHf[2 * jp][0] = r0; bHf[2 * jp][1] = r2;
            bHf[2 * jp + 1][0] = r1; bHf[2 * jp + 1][1] = r3;
            LDSM_X4(r0, r1, r2, r3, bd + PLANE_B);
            bLf[2 * jp][0] = r0; bLf[2 * jp][1] = r2;
            bLf[2 * jp + 1][0] = r1; bLf[2 * jp + 1][1] = r3;
        }
        // A hi pass: Ah*Bh + Ah*Bl
#pragma unroll
        for (int i = 0; i < 4; i++) {
            uint32_t ad = Ab + (wm + i * 16 + lrow) * 80 + kk * 32 + lcol;
            LDSM_X4(af[i][0], af[i][1], af[i][2], af[i][3], ad);
        }
#pragma unroll
        for (int i = 0; i < 4; i++)
#pragma unroll
            for (int j = 0; j < 4; j++) {
                MMA16816(acc[i][j][0], acc[i][j][1], acc[i][j][2], acc[i][j][3],
                         af[i][0], af[i][1], af[i][2], af[i][3], bHf[j][0], bHf[j][1]);
                MMA16816(acc[i][j][0], acc[i][j][1], acc[i][j][2], acc[i][j][3],
                         af[i][0], af[i][1], af[i][2], af[i][3], bLf[j][0], bLf[j][1]);
            }
        // A lo pass: Al*Bh (reuse fragment regs)
#pragma unroll
        for (int i = 0; i < 4; i++) {
            uint32_t ad = Ab + PLANE_B + (wm + i * 16 + lrow) * 80 + kk * 32 + lcol;
            LDSM_X4(af[i][0], af[i][1], af[i][2], af[i][3], ad);
        }
#pragma unroll
        for (int i = 0; i < 4; i++)
#pragma unroll
            for (int j = 0; j < 4; j++)
                MMA16816(acc[i][j][0], acc[i][j][1], acc[i][j][2], acc[i][j][3],
                         af[i][0], af[i][1], af[i][2], af[i][3], bHf[j][0], bHf[j][1]);
    }
}

__global__ __launch_bounds__(256, 2) void gate_gemm_kernel(int t) {
    extern __shared__ char smem[];
    uint32_t sb = smem_to_u32(smem);
    int tid = threadIdx.x, lane = tid & 31, wid = tid >> 5;
    // heavy gates first: [o, g, f, i]
    const int gate_order[4] = {2, 3, 1, 0};
    int gate = gate_order[blockIdx.x >> 8];
    int tile = blockIdx.x & 255;
    int n0 = (tile & 15) << 7, m0 = (tile >> 4) << 7;
    int nch = (gate == 0) ? 2 : (gate == 1) ? 18 : 24;
    int wm = (wid & 1) << 6, wn = (wid >> 1) << 5;

    const __nv_bfloat16* hHp = g_hH[t & 1];
    const __nv_bfloat16* hLp = g_hL[t & 1];

    float acc[4][4][4];
#pragma unroll
    for (int i = 0; i < 4; i++)
#pragma unroll
        for (int j = 0; j < 4; j++)
#pragma unroll
            for (int k = 0; k < 4; k++) acc[i][j][k] = 0.f;

    auto k0_of = [&](int ch) -> int {
        if (gate == 0) return 2048 + (ch << 5);
        if (gate == 1) return (ch < 16) ? (ch << 5) : (2112 + ((ch - 16) << 5));
        if (gate == 2) return 512 + (ch << 5);
        return 1280 + (ch << 5);
    };
    auto stage = [&](int buf, int k0) {
        const __nv_bfloat16 *aH, *aL;
        long astr;
        if (k0 < 2048) {
            aH = hHp + (long)m0 * NH + k0;
            aL = hLp + (long)m0 * NH + k0;
            astr = NH;
        } else {
            int off = (k0 - 2048) & 63;
            aH = g_encH + (long)m0 * TE + (long)t * 64 + off;
            aL = g_encL + (long)m0 * TE + (long)t * 64 + off;
            astr = TE;
        }
        stage_chunk(sb, buf, tid, aH, aL, astr,
                    g_WbH + (long)n0 * KP + k0, g_WbL + (long)n0 * KP + k0);
    };

    stage(0, k0_of(0));
    CP_COMMIT();
    for (int ch = 0; ch < nch; ch++) {
        if (ch + 1 < nch) {
            stage((ch + 1) & 1, k0_of(ch + 1));
            CP_COMMIT();
            CP_WAIT(1);
        } else {
            CP_WAIT(0);
        }
        __syncthreads();
        compute_chunk(sb, ch & 1, lane, wm, wn, acc);
        __syncthreads();
    }

    // write fp32 preacts
    float* prep = g_pre + (long)gate * BATCH * NH;
    int g = lane >> 2, tk = lane & 3;
#pragma unroll
    for (int i = 0; i < 4; i++) {
        int m = m0 + wm + i * 16 + g;
#pragma unroll
        for (int j = 0; j < 4; j++) {
            int n = n0 + wn + j * 8 + tk * 2;
            *(float2*)&prep[(long)m * NH + n]       = make_float2(acc[i][j][0], acc[i][j][1]);
            *(float2*)&prep[(long)(m + 8) * NH + n] = make_float2(acc[i][j][2], acc[i][j][3]);
        }
    }
}

// ================= Phase B: elementwise LSTM update =================
__global__ __launch_bounds__(256) void lstm_update_kernel(int t) {
    const long SZ = (long)BATCH * NH;
    long i4 = ((long)blockIdx.x * 256 + threadIdx.x) * 4;
    int n = (int)(i4 & (NH - 1));
    float4 vi = *(const float4*)&g_pre[i4];
    float4 vf = *(const float4*)&g_pre[SZ + i4];
    float4 vo = *(const float4*)&g_pre[2 * SZ + i4];
    float4 vg = *(const float4*)&g_pre[3 * SZ + i4];
    float4 bi = *(const float4*)&g_bias[n];
    float4 bf = *(const float4*)&g_bias[NH + n];
    float4 bo = *(const float4*)&g_bias[2 * NH + n];
    float4 bg = *(const float4*)&g_bias[3 * NH + n];
    float4 cc = *(const float4*)&g_c[i4];

    float pi[4] = {vi.x + bi.x, vi.y + bi.y, vi.z + bi.z, vi.w + bi.w};
    float pf[4] = {vf.x + bf.x, vf.y + bf.y, vf.z + bf.z, vf.w + bf.w};
    float po[4] = {vo.x + bo.x, vo.y + bo.y, vo.z + bo.z, vo.w + bo.w};
    float pg[4] = {vg.x + bg.x, vg.y + bg.y, vg.z + bg.z, vg.w + bg.w};
    float cv[4] = {cc.x, cc.y, cc.z, cc.w};
    float hn[4], cn[4];
#pragma unroll
    for (int j = 0; j < 4; j++) {
        float si = 1.f / (1.f + __expf(-pi[j]));
        float sf = 1.f / (1.f + __expf(-pf[j]));
        float so = 1.f / (1.f + __expf(-po[j]));
        float tg = tanhf(pg[j]);
        cn[j] = sf * cv[j] + si * tg;
        hn[j] = so * tanhf(cn[j]);
    }
    *(float4*)&g_c[i4] = make_float4(cn[0], cn[1], cn[2], cn[3]);

    __nv_bfloat16 hh[4], hl[4];
#pragma unroll
    for (int j = 0; j < 4; j++) {
        hh[j] = __float2bfloat16_rn(hn[j]);
        hl[j] = __float2bfloat16_rn(hn[j] - __bfloat162float(hh[j]));
    }
    int ob = (t + 1) & 1;
    *(uint2*)&g_hH[ob][i4] = make_uint2(pack_bf2(hh[0], hh[1]), pack_bf2(hh[2], hh[3]));
    *(uint2*)&g_hL[ob][i4] = make_uint2(pack_bf2(hl[0], hl[1]), pack_bf2(hl[2], hl[3]));
}

// ---------------- classifier: h_last[2048,2048] -> relu FC 128 -> FC 2
__global__ void cls_kernel(const float* __restrict__ w1, const float* __restrict__ b1,
                           const float* __restrict__ w2, const float* __restrict__ b2,
                           float* __restrict__ out) {
    __shared__ float hs[4][NH];
    __shared__ float hid[4][128];
    int tid = threadIdx.x;
    int b0 = blockIdx.x * 4;
    const __nv_bfloat16* hH = g_hH[0];   // after 128 steps (t=127 writes buf 0)
    const __nv_bfloat16* hL = g_hL[0];

    for (int i = tid; i < 4 * NH; i += 128) {
        long idx = (long)(b0 + (i >> 11)) * NH + (i & 2047);
        hs[i >> 11][i & 2047] = __bfloat162float(hH[idx]) + __bfloat162float(hL[idx]);
    }
    __syncthreads();

    int wid = tid >> 5, lane = tid & 31;
    for (int jj = 0; jj < 32; jj++) {
        int j = wid * 32 + jj;
        float p0 = 0.f, p1 = 0.f, p2 = 0.f, p3 = 0.f;
        const float* wr = w1 + (long)j * NH;
        for (int k = lane; k < NH; k += 32) {
            float wv = wr[k];
            p0 += wv * hs[0][k]; p1 += wv * hs[1][k];
            p2 += wv * hs[2][k]; p3 += wv * hs[3][k];
        }
#pragma unroll
        for (int off = 16; off; off >>= 1) {
            p0 += __shfl_xor_sync(0xffffffffu, p0, off);
            p1 += __shfl_xor_sync(0xffffffffu, p1, off);
            p2 += __shfl_xor_sync(0xffffffffu, p2, off);
            p3 += __shfl_xor_sync(0xffffffffu, p3, off);
        }
        if (lane == 0) {
            float bb = b1[j];
            hid[0][j] = fmaxf(p0 + bb, 0.f);
            hid[1][j] = fmaxf(p1 + bb, 0.f);
            hid[2][j] = fmaxf(p2 + bb, 0.f);
            hid[3][j] = fmaxf(p3 + bb, 0.f);
        }
    }
    __syncthreads();
    if (tid < 8) {
        int r = tid >> 1, k2 = tid & 1;
        float s = b2[k2];
        for (int j = 0; j < 128; j++) s += hid[r][j] * w2[k2 * 128 + j];
        out[(b0 + r) * 2 + k2] = s;
    }
}

extern "C" void kernel_launch(void* const* d_in, const int* in_sizes, int n_in,
                              void* d_out, int out_size) {
    const float* x        = (const float*)d_in[0];
    const float* conv1d_w = (const float*)d_in[1];
    const float* conv1d_b = (const float*)d_in[2];
    const float* bn_gamma = (const float*)d_in[3];
    const float* bn_beta  = (const float*)d_in[4];
    const float* bn_mean  = (const float*)d_in[5];
    const float* bn_var   = (const float*)d_in[6];
    const float* lin_w    = (const float*)d_in[7];
    const float* lin_b    = (const float*)d_in[8];
    const float* cell_w   = (const float*)d_in[9];
    const float* cell_b   = (const float*)d_in[10];
    const float* cls1_w   = (const float*)d_in[11];
    const float* cls1_b   = (const float*)d_in[12];
    const float* cls2_w   = (const float*)d_in[13];
    const float* cls2_b   = (const float*)d_in[14];
    float* out = (float*)d_out;

    static bool attr_set = false;
    if (!attr_set) {
        cudaFuncSetAttribute(gate_gemm_kernel,
                             cudaFuncAttributeMaxDynamicSharedMemorySize, STEP_SMEM);
        attr_set = true;
    }

    zero_kernel<<<4096, 256>>>();
    encoder_kernel<<<BATCH * T_STEPS / 4, 256>>>(x, conv1d_w, conv1d_b,
                                                 bn_gamma, bn_beta, bn_mean, bn_var);
    weff_kernel<<<256, 256>>>(lin_w);
    { dim3 g(8, 2048); wcat_conv_kernel<<<g, 256>>>(cell_w); }
    wcat_enc_kernel<<<2048, 128>>>(cell_w);
    bias_kernel<<<8, 256>>>(cell_w, cell_b, lin_b);

    for (int t = 0; t < T_STEPS; t++) {
        gate_gemm_kernel<<<1024, 256, STEP_SMEM>>>(t);
        lstm_update_kernel<<<BATCH * NH / 4 / 256, 256>>>(t);
    }

    cls_kernel<<<512, 128>>>(cls1_w, cls1_b, cls2_w, cls2_b, out);
}